// round 14
// baseline (speedup 1.0000x reference)
#include <cuda_runtime.h>
#include <cuda_fp16.h>
#include <cstdint>

#define BATCH   2
#define SEQ     2048
#define DMODEL  768
#define NHEADS  12
#define HEADDIM 64
#define KKEEP   614
#define TQ      128
#define NQT     (SEQ / TQ)
#define ATHREADS 512
#define MROWS   (BATCH * SEQ)     // 4096

// ---------------- device scratch (fp16 hi/lo splits) --------------------------
__device__ __align__(16) __half g_Xh[MROWS * DMODEL];
__device__ __align__(16) __half g_Xl[MROWS * DMODEL];
__device__ __align__(16) __half g_Wqh[DMODEL * DMODEL];
__device__ __align__(16) __half g_Wql[DMODEL * DMODEL];
__device__ __align__(16) __half g_Wkh[DMODEL * DMODEL];
__device__ __align__(16) __half g_Wkl[DMODEL * DMODEL];
__device__ __align__(16) __half g_Wvh[DMODEL * DMODEL];
__device__ __align__(16) __half g_Wvl[DMODEL * DMODEL];
__device__ __align__(16) __half g_Woh[DMODEL * DMODEL];
__device__ __align__(16) __half g_Wol[DMODEL * DMODEL];
__device__ __align__(16) __half g_Qh[BATCH * NHEADS * SEQ * HEADDIM];
__device__ __align__(16) __half g_Ql[BATCH * NHEADS * SEQ * HEADDIM];
__device__ __align__(16) __half g_Kh[BATCH * NHEADS * SEQ * HEADDIM];
__device__ __align__(16) __half g_Kl[BATCH * NHEADS * SEQ * HEADDIM];
__device__ __align__(16) __half g_Vth[BATCH * NHEADS * HEADDIM * SEQ];
__device__ __align__(16) __half g_Vtl[BATCH * NHEADS * HEADDIM * SEQ];
__device__ __align__(16) __half g_Oh[MROWS * DMODEL];
__device__ __align__(16) __half g_Ol[MROWS * DMODEL];
__device__ __align__(16) float g_S[(size_t)BATCH * NHEADS * SEQ * SEQ];
__device__ __align__(16) __half g_P[(size_t)BATCH * NHEADS * SEQ * SEQ];

// fp16 inputs, fp32 accum (main term)
#define MMA16816(c, a, b)                                                        \
    asm volatile("mma.sync.aligned.m16n8k16.row.col.f32.f16.f16.f32 "            \
        "{%0,%1,%2,%3}, {%4,%5,%6,%7}, {%8,%9}, {%0,%1,%2,%3};"                  \
        : "+f"((c)[0]), "+f"((c)[1]), "+f"((c)[2]), "+f"((c)[3])                 \
        : "r"((a)[0]), "r"((a)[1]), "r"((a)[2]), "r"((a)[3]),                    \
          "r"((b)[0]), "r"((b)[1]))

// fp16 inputs, fp16 accum (cross terms; magnitudes ~2^-11 of main)
#define MMAH(c, a, b)                                                            \
    asm volatile("mma.sync.aligned.m16n8k16.row.col.f16.f16.f16.f16 "            \
        "{%0,%1}, {%2,%3,%4,%5}, {%6,%7}, {%0,%1};"                              \
        : "+r"((c)[0]), "+r"((c)[1])                                             \
        : "r"((a)[0]), "r"((a)[1]), "r"((a)[2]), "r"((a)[3]),                    \
          "r"((b)[0]), "r"((b)[1]))

#define LDSM_X4(r, addr)                                                         \
    asm volatile("ldmatrix.sync.aligned.m8n8.x4.shared.b16 {%0,%1,%2,%3}, [%4];" \
        : "=r"((r)[0]), "=r"((r)[1]), "=r"((r)[2]), "=r"((r)[3]) : "r"(addr))

#define LDSM_X2(r, addr)                                                         \
    asm volatile("ldmatrix.sync.aligned.m8n8.x2.shared.b16 {%0,%1}, [%2];"       \
        : "=r"((r)[0]), "=r"((r)[1]) : "r"(addr))

static __device__ __forceinline__ uint32_t smem_u32(const void* p) {
    uint32_t a;
    asm("{ .reg .u64 t; cvta.to.shared.u64 t, %1; cvt.u32.u64 %0, t; }" : "=r"(a) : "l"(p));
    return a;
}
static __device__ __forceinline__ void cp16(uint32_t dst, const void* src) {
    asm volatile("cp.async.ca.shared.global [%0], [%1], 16;" :: "r"(dst), "l"(src));
}
#define CP_COMMIT() asm volatile("cp.async.commit_group;" ::: "memory")
#define CP_WAIT1()  asm volatile("cp.async.wait_group 1;" ::: "memory")
#define CP_WAIT0()  asm volatile("cp.async.wait_group 0;" ::: "memory")

static __device__ __forceinline__ uint32_t pack_hl(float a, float b, float* ra, float* rb) {
    __half ha = __float2half_rn(a), hb = __float2half_rn(b);
    *ra = a - __half2float(ha);
    *rb = b - __half2float(hb);
    return ((uint32_t)__half_as_ushort(hb) << 16) | __half_as_ushort(ha);
}
static __device__ __forceinline__ uint32_t pack_h(float a, float b) {
    return ((uint32_t)__half_as_ushort(__float2half_rn(b)) << 16)
         | __half_as_ushort(__float2half_rn(a));
}
static __device__ __forceinline__ float2 h2f2(uint32_t p) {
    __half2 h = *reinterpret_cast<__half2*>(&p);
    return make_float2(__low2float(h), __high2float(h));
}
__device__ __forceinline__ uint32_t f2key(float f) {
    uint32_t u = __float_as_uint(f);
    return (u & 0x80000000u) ? ~u : (u | 0x80000000u);
}

// ---------------- fp32 -> fp16 hi/lo convert (ptrs as kernel args) ------------
__global__ __launch_bounds__(256) void cvt_kernel(
    const float* x, const float* wq, const float* wk, const float* wv, const float* wo,
    int nx4, int nw4)
{
    int t = blockIdx.y;
    int i = blockIdx.x * 256 + threadIdx.x;
    const float* s;
    __half *dh, *dl;
    int n4;
    switch (t) {
        case 0:  s = x;  dh = g_Xh;  dl = g_Xl;  n4 = nx4; break;
        case 1:  s = wq; dh = g_Wqh; dl = g_Wql; n4 = nw4; break;
        case 2:  s = wk; dh = g_Wkh; dl = g_Wkl; n4 = nw4; break;
        case 3:  s = wv; dh = g_Wvh; dl = g_Wvl; n4 = nw4; break;
        default: s = wo; dh = g_Woh; dl = g_Wol; n4 = nw4; break;
    }
    if (i >= n4) return;
    float4 v = ((const float4*)s)[i];
    float lx, ly, lz, lw;
    uint32_t h0 = pack_hl(v.x, v.y, &lx, &ly);
    uint32_t h1 = pack_hl(v.z, v.w, &lz, &lw);
    ((uint32_t*)dh)[i * 2]     = h0;
    ((uint32_t*)dh)[i * 2 + 1] = h1;
    ((uint32_t*)dl)[i * 2]     = pack_h(lx, ly);
    ((uint32_t*)dl)[i * 2 + 1] = pack_h(lz, lw);
}

// ---------------- projection GEMM: fp16x3 warp-mma + ldmatrix -----------------
#define PROJ_DYN 147456

__global__ __launch_bounds__(512) void proj_mma_kernel(
    int oproj,
    const float* __restrict__ bq, const float* __restrict__ bk,
    const float* __restrict__ bv, const float* __restrict__ bo,
    float* __restrict__ y)
{
    extern __shared__ __align__(16) uint32_t sm32[];

    const int tid   = threadIdx.x;
    const int lane  = tid & 31, w = tid >> 5;
    const int group = lane >> 2, qd = lane & 3;
    const int wm    = w & 7, wn = w >> 3;
    const int n0    = blockIdx.x * 128;
    const int m0    = blockIdx.y * 128;
    const int z     = oproj ? 3 : blockIdx.z;

    const uint32_t *Ah32, *Al32, *Bh32, *Bl32;
    const float* bias;
    if (oproj) { Ah32 = (const uint32_t*)g_Oh; Al32 = (const uint32_t*)g_Ol;
                 Bh32 = (const uint32_t*)g_Woh; Bl32 = (const uint32_t*)g_Wol; bias = bo; }
    else {
        Ah32 = (const uint32_t*)g_Xh; Al32 = (const uint32_t*)g_Xl;
        if (z == 0)      { Bh32 = (const uint32_t*)g_Wqh; Bl32 = (const uint32_t*)g_Wql; bias = bq; }
        else if (z == 1) { Bh32 = (const uint32_t*)g_Wkh; Bl32 = (const uint32_t*)g_Wkl; bias = bk; }
        else             { Bh32 = (const uint32_t*)g_Wvh; Bl32 = (const uint32_t*)g_Wvl; bias = bv; }
    }

    const uint32_t smb = smem_u32(sm32);
    const int r0 = wm * 16 + group;

    const uint32_t aOff = (((wm * 16 + (lane & 15)) * 36 + ((lane >> 4) << 2)) << 2);
    const uint32_t bOff = (((wn * 64 + (lane & 7)) * 36 + (((lane >> 3) & 1) << 2)) << 2);

    auto loadChunk = [&](int blk, int buf) {
        const int koff = blk * 32;
#pragma unroll
        for (int it = 0; it < 8; ++it) {
            int idx = tid + it * 512;
            int sel = idx >> 11;
            int arr = (idx >> 10) & 1;
            int rem = idx & 1023;
            int r = rem >> 3, ch = rem & 7;
            uint32_t dst = smb + (buf * 18432 + sel * 9216 + arr * 4608 + r * 36 + ch * 4) * 4;
            const uint32_t* src;
            if (sel == 0) src = (arr ? Al32 : Ah32) + (size_t)(m0 + r) * 384 + koff + ch * 4;
            else          src = (arr ? Bl32 : Bh32) + (size_t)(n0 + r) * 384 + koff + ch * 4;
            cp16(dst, src);
        }
    };

    float c8[8][4];
    uint32_t chf[8][2];
#pragma unroll
    for (int nt = 0; nt < 8; ++nt) {
#pragma unroll
        for (int i = 0; i < 4; ++i) c8[nt][i] = 0.f;
        chf[nt][0] = 0u; chf[nt][1] = 0u;
    }

    loadChunk(0, 0); CP_COMMIT();

    for (int blk = 0; blk < 12; ++blk) {
        __syncthreads();
        if (blk + 1 < 12) { loadChunk(blk + 1, (blk + 1) & 1); CP_COMMIT(); CP_WAIT1(); }
        else              { CP_WAIT0(); }
        __syncthreads();

        const uint32_t bufb = smb + ((blk & 1) * 18432 << 2);
        const uint32_t aH = bufb + aOff;
        const uint32_t aL = aH + (4608 << 2);
        const uint32_t bH = bufb + (9216 << 2) + bOff;
        const uint32_t bL = bH + (4608 << 2);

#pragma unroll
        for (int ks = 0; ks < 4; ++ks) {
            uint32_t ah[4], al[4];
            LDSM_X4(ah, aH + ks * 32);
            LDSM_X4(al, aL + ks * 32);
#pragma unroll
            for (int nt = 0; nt < 8; ++nt) {
                uint32_t bhv[2], blv[2];
                LDSM_X2(bhv, bH + nt * 1152 + ks * 32);
                LDSM_X2(blv, bL + nt * 1152 + ks * 32);
                MMA16816(c8[nt], ah, bhv);
                MMAH(chf[nt], ah, blv);
                MMAH(chf[nt], al, bhv);
            }
        }
    }

#pragma unroll
    for (int nt = 0; nt < 8; ++nt) {
        float2 x0 = h2f2(chf[nt][0]);
        float2 x1 = h2f2(chf[nt][1]);
        int n = n0 + wn * 64 + nt * 8 + qd * 2;
        float b0 = bias[n], b1 = bias[n + 1];
        int ma = m0 + r0, mb = ma + 8;
        float v00 = c8[nt][0] + x0.x + b0, v01 = c8[nt][1] + x0.y + b1;
        float v10 = c8[nt][2] + x1.x + b0, v11 = c8[nt][3] + x1.y + b1;
        if (oproj) {
            *(float2*)(y + (size_t)ma * DMODEL + n) = make_float2(v00, v01);
            *(float2*)(y + (size_t)mb * DMODEL + n) = make_float2(v10, v11);
        } else {
            int h = n >> 6, e = n & 63;
            if (z < 2) {
                __half* dh = (z == 0) ? g_Qh : g_Kh;
                __half* dl = (z == 0) ? g_Ql : g_Kl;
                int ba = ma >> 11, sa = ma & (SEQ - 1);
                int bb = mb >> 11, sb = mb & (SEQ - 1);
                size_t oa = ((((size_t)(ba * NHEADS + h)) * SEQ + sa) * HEADDIM + e) >> 1;
                size_t ob = ((((size_t)(bb * NHEADS + h)) * SEQ + sb) * HEADDIM + e) >> 1;
                float la, lb2, lc, ld;
                ((uint32_t*)dh)[oa] = pack_hl(v00, v01, &la, &lb2);
                ((uint32_t*)dl)[oa] = pack_h(la, lb2);
                ((uint32_t*)dh)[ob] = pack_hl(v10, v11, &lc, &ld);
                ((uint32_t*)dl)[ob] = pack_h(lc, ld);
            } else {
                int ba = ma >> 11, sa = ma & (SEQ - 1);
                int bb = mb >> 11, sb = mb & (SEQ - 1);
                size_t base0 = (((size_t)(ba * NHEADS + h)) * HEADDIM + e) * SEQ;
                size_t base1 = (((size_t)(bb * NHEADS + h)) * HEADDIM + e) * SEQ;
                __half h00 = __float2half_rn(v00); float l0 = v00 - __half2float(h00);
                __half h01 = __float2half_rn(v01); float l1 = v01 - __half2float(h01);
                __half h10 = __float2half_rn(v10); float l2 = v10 - __half2float(h10);
                __half h11 = __float2half_rn(v11); float l3 = v11 - __half2float(h11);
                g_Vth[base0 + sa]       = h00; g_Vtl[base0 + sa]       = __float2half_rn(l0);
                g_Vth[base0 + SEQ + sa] = h01; g_Vtl[base0 + SEQ + sa] = __float2half_rn(l1);
                g_Vth[base1 + sb]       = h10; g_Vtl[base1 + sb]       = __float2half_rn(l2);
                g_Vth[base1 + SEQ + sb] = h11; g_Vtl[base1 + SEQ + sb] = __float2half_rn(l3);
            }
        }
    }
}

// ---------------- attention (fused; compaction radix select) ------------------
#define DYN_BYTES 147456

__global__ __launch_bounds__(ATHREADS) void attn_kernel()
{
    extern __shared__ __align__(16) uint32_t sm32[];

    __shared__ float s_inv[TQ];

    const int tid   = threadIdx.x;
    const int lane  = tid & 31, w = tid >> 5;
    const int group = lane >> 2, qd = lane & 3;
    const int wm    = w & 7;
    const int wn    = w >> 3;
    const int qt    = blockIdx.x & (NQT - 1);
    const int bh    = blockIdx.x >> 4;
    const int qrow0 = qt * TQ;

    const size_t hb = (size_t)bh * SEQ * HEADDIM;
    const uint32_t* qh32 = (const uint32_t*)(g_Qh + hb) + (size_t)qrow0 * 32;
    const uint32_t* ql32 = (const uint32_t*)(g_Ql + hb) + (size_t)qrow0 * 32;
    const uint32_t* kh32 = (const uint32_t*)(g_Kh + hb);
    const uint32_t* kl32 = (const uint32_t*)(g_Kl + hb);
    const uint32_t* vh32 = (const uint32_t*)(g_Vth + hb);
    const uint32_t* vl32 = (const uint32_t*)(g_Vtl + hb);
    float* Sp = g_S + (size_t)blockIdx.x * TQ * SEQ;
    uint32_t* Pp = (uint32_t*)g_P + (size_t)blockIdx.x * TQ * (SEQ / 2);

    const uint32_t smb = smem_u32(sm32);
    const int r0 = wm * 16 + group;

    // ================= phase 1: S = Q@K^T * 0.125 -> g_S ====================
    {
        uint32_t* QH = sm32;
        uint32_t* QL = sm32 + 4608;

#pragma unroll
        for (int it = 0; it < 8; ++it) {
            int idx = tid + it * ATHREADS;
            int r = idx >> 5, c = idx & 31;
            QH[r * 36 + c] = qh32[(size_t)r * 32 + c];
            QL[r * 36 + c] = ql32[(size_t)r * 32 + c];
        }

        auto loadK = [&](int blk, int buf) {
            const int j0 = blk * 128;
            const uint32_t dstb = smb + (9216 + buf * 9216) * 4;
#pragma unroll
            for (int it = 0; it < 4; ++it) {
                int idx = tid + it * ATHREADS;
                int arr = idx >> 10, rem = idx & 1023;
                int r = rem >> 3, ch = rem & 7;
                uint32_t dst = dstb + (arr * 4608 + r * 36 + ch * 4) * 4;
                const uint32_t* src = (arr ? kl32 : kh32) + (size_t)(j0 + r) * 32 + ch * 4;
                cp16(dst, src);
            }
        };

        const uint32_t aH = smb + (((wm * 16 + (lane & 15)) * 36 + ((lane >> 4) << 2)) << 2);
        const uint32_t aL = aH + (4608 << 2);
        const uint32_t bOff = (((wn * 64 + (lane & 7)) * 36 + (((lane >> 3) & 1) << 2)) << 2);

        loadK(0, 0); CP_COMMIT();
        __syncthreads();                         // Q tile visible

        uint32_t qfh[4][4], qfl[4][4];
#pragma unroll
        for (int ks = 0; ks < 4; ++ks) {
            LDSM_X4(qfh[ks], aH + ks * 32);
            LDSM_X4(qfl[ks], aL + ks * 32);
        }

        for (int blk = 0; blk < 16; ++blk) {
            __syncthreads();
            if (blk + 1 < 16) { loadK(blk + 1, (blk + 1) & 1); CP_COMMIT(); CP_WAIT1(); }
            else              { CP_WAIT0(); }
            __syncthreads();

            const uint32_t bH = smb + ((9216 + (blk & 1) * 9216) << 2) + bOff;
            const uint32_t bL = bH + (4608 << 2);
            const int j0 = blk * 128;

            float c8[8][4];
            uint32_t chf[8][2];
#pragma unroll
            for (int nt = 0; nt < 8; ++nt) {
#pragma unroll
                for (int i = 0; i < 4; ++i) c8[nt][i] = 0.f;
                chf[nt][0] = 0u; chf[nt][1] = 0u;
            }

#pragma unroll
            for (int ks = 0; ks < 4; ++ks) {
#pragma unroll
                for (int nt = 0; nt < 8; ++nt) {
                    uint32_t bhv[2], blv[2];
                    LDSM_X2(bhv, bH + nt * 1152 + ks * 32);
                    LDSM_X2(blv, bL + nt * 1152 + ks * 32);
                    MMA16816(c8[nt], qfh[ks], bhv);
                    MMAH(chf[nt], qfh[ks], blv);
                    MMAH(chf[nt], qfl[ks], bhv);
                }
            }
#pragma unroll
            for (int nt = 0; nt < 8; ++nt) {
                float2 x0 = h2f2(chf[nt][0]);
                float2 x1 = h2f2(chf[nt][1]);
                int col = j0 + wn * 64 + nt * 8 + qd * 2;
                float2 v0 = { (c8[nt][0] + x0.x) * 0.125f, (c8[nt][1] + x0.y) * 0.125f };
                float2 v1 = { (c8[nt][2] + x1.x) * 0.125f, (c8[nt][3] + x1.y) * 0.125f };
                *(float2*)(Sp + (size_t)r0 * SEQ + col)       = v0;
                *(float2*)(Sp + (size_t)(r0 + 8) * SEQ + col) = v1;
            }
        }
    }
    __syncthreads();

    // ====== phase 2: compaction radix top-k; unnormalized fp16 P -> g_P =====
    {
        uint32_t* kb   = sm32 + w * 2048;              // key buffer, 8 KB/warp
        uint32_t* hist = sm32 + 32768 + w * 256;
        const uint32_t lmask = (1u << lane) - 1u;

        for (int i = lane; i < 256; i += 32) hist[i] = 0;
        __syncwarp();

        for (int t = 0; t < 8; ++t) {
            int r = w * 8 + t;
            const float2* g2 = (const float2*)(Sp + (size_t)r * SEQ);

            // ---- pass A: load, max, keys->kb, hist of byte3 ----
            float mx = -3.4e38f;
            for (int it = 0; it < 32; ++it) {
                float2 s2 = g2[it * 32 + lane];
                mx = fmaxf(mx, fmaxf(s2.x, s2.y));
                uint32_t k0 = f2key(s2.x), k1 = f2key(s2.y);
                ((uint2*)kb)[it * 32 + lane] = make_uint2(k0, k1);
                int b0 = k0 >> 24;
                unsigned p = __match_any_sync(0xffffffffu, b0);
                if ((int)__ffs(p) - 1 == lane) atomicAdd(&hist[b0], (uint32_t)__popc(p));
                int b1 = k1 >> 24;
                p = __match_any_sync(0xffffffffu, b1);
                if ((int)__ffs(p) - 1 == lane) atomicAdd(&hist[b1], (uint32_t)__popc(p));
            }
#pragma unroll
            for (int off = 16; off; off >>= 1)
                mx = fmaxf(mx, __shfl_xor_sync(0xffffffffu, mx, off));
            __syncwarp();

            // ---- radix passes with in-place compaction ----
            uint32_t prefix = 0;
            int want = KKEEP;
            int n = SEQ;
#pragma unroll
            for (int pass = 0; pass < 4; ++pass) {
                const int shift = 24 - pass * 8;
                // resolve digit
                int c[8]; int lsum = 0;
#pragma unroll
                for (int i = 0; i < 8; ++i) { c[i] = (int)hist[lane * 8 + i]; lsum += c[i]; }
                int incl = lsum;
#pragma unroll
                for (int off = 1; off < 32; off <<= 1) {
                    int tt = __shfl_up_sync(0xffffffffu, incl, off);
                    if (lane >= off) incl += tt;
                }
                int total = __shfl_sync(0xffffffffu, incl, 31);
                int run = total - incl;
                int fd = -1, fw = 0;
#pragma unroll
                for (int i = 7; i >= 0; --i) {
                    if (run < want && run + c[i] >= want) { fd = lane * 8 + i; fw = want - run; }
                    run += c[i];
                }
                unsigned bal2 = __ballot_sync(0xffffffffu, fd >= 0);
                int src = __ffs(bal2) - 1;
                fd   = __shfl_sync(0xffffffffu, fd, src);
                want = __shfl_sync(0xffffffffu, fw, src);
                prefix |= (uint32_t)fd << shift;
                __syncwarp();
                for (int i = lane; i < 256; i += 32) hist[i] = 0;
                __syncwarp();
                if (pass == 3) break;

                // compact survivors (digit==fd at shift) in place; hist next byte
                const int nshift = shift - 8;
                int n2 = 0;
                const int iters = (n + 31) >> 5;
                for (int it = 0; it < iters; ++it) {
                    int i = it * 32 + lane;
                    bool inb = i < n;
                    uint32_t k = inb ? kb[i] : 0u;
                    __syncwarp();                       // all reads before writes
                    bool act = inb && (((k >> shift) & 0xFFu) == (uint32_t)fd);
                    unsigned bal = __ballot_sync(0xffffffffu, act);
                    int pos = n2 + __popc(bal & lmask);
                    if (act) {
                        kb[pos] = k;
                        int nb = (k >> nshift) & 0xFF;
                        unsigned peers = __match_any_sync(bal, nb);
                        if ((int)__ffs(peers) - 1 == lane)
                            atomicAdd(&hist[nb], (uint32_t)__popc(peers));
                    }
                    n2 += __popc(bal);
                }
                n = n2;
                __syncwarp();
            }
            const uint32_t thr = prefix;

            // ---- pass E: exp + sum + P (re-read S from gmem) ----
            float sum = 0.f;
            uint32_t* gpr = Pp + (size_t)r * (SEQ / 2);
            for (int it = 0; it < 32; ++it) {
                float2 s2 = g2[it * 32 + lane];
                float e0 = (f2key(s2.x) >= thr) ? __expf(s2.x - mx) : 0.f;
                float e1 = (f2key(s2.y) >= thr) ? __expf(s2.y - mx) : 0.f;
                sum += e0 + e1;
                gpr[it * 32 + lane] = pack_h(e0, e1);
            }
#pragma unroll
            for (int off = 16; off; off >>= 1)
                sum += __shfl_xor_sync(0xffffffffu, sum, off);
            if (lane == 0) s_inv[r] = 1.0f / sum;
            __syncwarp();
        }
    }
    __syncthreads();

    // ============ phase 3: O = (P @ (Vh+Vl)) * inv  (pure GEMM) =============
    {
        auto loadPV = [&](int blk, int buf) {
            const int j32 = blk * 64;
            const uint32_t pdst = smb + (buf * 8704) * 4;
#pragma unroll
            for (int it = 0; it < 4; ++it) {
                int idx = tid + it * ATHREADS;
                int r = idx >> 4, ch = idx & 15;
                cp16(pdst + (r * 68 + ch * 4) * 4,
                     Pp + (size_t)r * (SEQ / 2) + j32 + ch * 4);
            }
            const uint32_t vdst = smb + (17408 + buf * 8704) * 4;
#pragma unroll
            for (int it = 0; it < 4; ++it) {
                int idx = tid + it * ATHREADS;
                int arr = idx >> 10, rem = idx & 1023;
                int r = rem >> 4, ch = rem & 15;
                cp16(vdst + (arr * 4352 + r * 68 + ch * 4) * 4,
                     (arr ? vl32 : vh32) + (size_t)r * 1024 + j32 + ch * 4);
            }
        };

        float c8[4][4];
#pragma unroll
        for (int nt = 0; nt < 4; ++nt)
#pragma unroll
            for (int i = 0; i < 4; ++i) c8[nt][i] = 0.f;

        const uint32_t aOff3 = (((wm * 16 + (lane & 15)) * 68 + ((lane >> 4) << 2)) << 2);
        const uint32_t bOff3 = (((wn * 32 + (lane & 7)) * 68 + (((lane >> 3) & 1) << 2)) << 2);

        loadPV(0, 0); CP_COMMIT();

        for (int blk = 0; blk < 16; ++blk) {
            __syncthreads();
            if (blk + 1 < 16) { loadPV(blk + 1, (blk + 1) & 1); CP_COMMIT(); CP_WAIT1(); }
            else              { CP_WAIT0(); }
            __syncthreads();

            const uint32_t aP  = smb + (((blk & 1) * 8704) << 2) + aOff3;
            const uint32_t bH3 = smb + ((17408 + (blk & 1) * 8704) << 2) + bOff3;
            const uint32_t bL3 = bH3 + (4352 << 2);

#pragma unroll
            for (int ks = 0; ks < 8; ++ks) {
                uint32_t ah[4];
                LDSM_X4(ah, aP + ks * 32);
#pragma unroll
                for (int nt = 0; nt < 4; ++nt) {
                    uint32_t bhv[2], blv[2];
                    LDSM_X2(bhv, bH3 + nt * 2176 + ks * 32);
                    LDSM_X2(blv, bL3 + nt * 2176 + ks * 32);
                    MMA16816(c8[nt], ah, bhv);
                    MMA16816(c8[nt], ah, blv);
                }
            }
        }

        const int b_ = bh / NHEADS, h = bh % NHEADS;
        const float inv0 = s_inv[r0], inv1 = s_inv[r0 + 8];
#pragma unroll
        for (int nt = 0; nt < 4; ++nt) {
            int e = h * HEADDIM + wn * 32 + nt * 8 + qd * 2;
            int s0 = qrow0 + r0, s1 = s0 + 8;
            size_t o0 = (((size_t)(b_ * SEQ + s0)) * DMODEL + e) >> 1;
            size_t o1 = (((size_t)(b_ * SEQ + s1)) * DMODEL + e) >> 1;
            float l0, l1, l2, l3;
            ((uint32_t*)g_Oh)[o0] = pack_hl(c8[nt][0] * inv0, c8[nt][1] * inv0, &l0, &l1);
            ((uint32_t*)g_Ol)[o0] = pack_h(l0, l1);
            ((uint32_t*)g_Oh)[o1] = pack_hl(c8[nt][2] * inv1, c8[nt][3] * inv1, &l2, &l3);
            ((uint32_t*)g_Ol)[o1] = pack_h(l2, l3);
        }
    }
}

// ---------------- launch ------------------------------------------------------
extern "C" void kernel_launch(void* const* d_in, const int* in_sizes, int n_in,
                              void* d_out, int out_size)
{
    const float* x  = (const float*)d_in[0];
    const float* Wq = (const float*)d_in[1];
    const float* bq = (const float*)d_in[2];
    const float* Wk = (const float*)d_in[3];
    const float* bk = (const float*)d_in[4];
    const float* Wv = (const float*)d_in[5];
    const float* bv = (const float*)d_in[6];
    const float* Wo = (const float*)d_in[7];
    const float* bo = (const float*)d_in[8];
    float* y = (float*)d_out;

    const int nx4 = MROWS * DMODEL / 4;
    const int nw4 = DMODEL * DMODEL / 4;

    dim3 gc((nx4 + 255) / 256, 5);
    cvt_kernel<<<gc, 256>>>(x, Wq, Wk, Wv, Wo, nx4, nw4);

    cudaFuncSetAttribute(proj_mma_kernel, cudaFuncAttributeMaxDynamicSharedMemorySize, PROJ_DYN);
    dim3 gq(DMODEL / 128, MROWS / 128, 3);
    proj_mma_kernel<<<gq, 512, PROJ_DYN>>>(0, bq, bk, bv, bo, y);

    cudaFuncSetAttribute(attn_kernel, cudaFuncAttributeMaxDynamicSharedMemorySize, DYN_BYTES);
    attn_kernel<<<BATCH * NHEADS * NQT, ATHREADS, DYN_BYTES>>>();

    dim3 go(DMODEL / 128, MROWS / 128, 1);
    proj_mma_kernel<<<go, 512, PROJ_DYN>>>(1, bq, bk, bv, bo, y);
}

// round 16
// speedup vs baseline: 1.2438x; 1.2438x over previous
#include <cuda_runtime.h>
#include <cuda_fp16.h>
#include <cstdint>

#define BATCH   2
#define SEQ     2048
#define DMODEL  768
#define NHEADS  12
#define HEADDIM 64
#define KKEEP   614
#define TQ      128
#define NQT     (SEQ / TQ)
#define ATHREADS 512
#define MROWS   (BATCH * SEQ)     // 4096

// ---------------- device scratch (fp16 hi/lo splits) --------------------------
__device__ __align__(16) __half g_Xh[MROWS * DMODEL];
__device__ __align__(16) __half g_Xl[MROWS * DMODEL];
__device__ __align__(16) __half g_Wqh[DMODEL * DMODEL];
__device__ __align__(16) __half g_Wql[DMODEL * DMODEL];
__device__ __align__(16) __half g_Wkh[DMODEL * DMODEL];
__device__ __align__(16) __half g_Wkl[DMODEL * DMODEL];
__device__ __align__(16) __half g_Wvh[DMODEL * DMODEL];
__device__ __align__(16) __half g_Wvl[DMODEL * DMODEL];
__device__ __align__(16) __half g_Woh[DMODEL * DMODEL];
__device__ __align__(16) __half g_Wol[DMODEL * DMODEL];
__device__ __align__(16) __half g_Qh[BATCH * NHEADS * SEQ * HEADDIM];
__device__ __align__(16) __half g_Ql[BATCH * NHEADS * SEQ * HEADDIM];
__device__ __align__(16) __half g_Kh[BATCH * NHEADS * SEQ * HEADDIM];
__device__ __align__(16) __half g_Kl[BATCH * NHEADS * SEQ * HEADDIM];
__device__ __align__(16) __half g_Vth[BATCH * NHEADS * HEADDIM * SEQ];
__device__ __align__(16) __half g_Vtl[BATCH * NHEADS * HEADDIM * SEQ];
__device__ __align__(16) __half g_Oh[MROWS * DMODEL];
__device__ __align__(16) __half g_Ol[MROWS * DMODEL];
__device__ __align__(16) float g_S[(size_t)BATCH * NHEADS * SEQ * SEQ];
__device__ __align__(16) __half g_P[(size_t)BATCH * NHEADS * SEQ * SEQ];

// fp16 inputs, fp32 accum (main term)
#define MMA16816(c, a, b)                                                        \
    asm volatile("mma.sync.aligned.m16n8k16.row.col.f32.f16.f16.f32 "            \
        "{%0,%1,%2,%3}, {%4,%5,%6,%7}, {%8,%9}, {%0,%1,%2,%3};"                  \
        : "+f"((c)[0]), "+f"((c)[1]), "+f"((c)[2]), "+f"((c)[3])                 \
        : "r"((a)[0]), "r"((a)[1]), "r"((a)[2]), "r"((a)[3]),                    \
          "r"((b)[0]), "r"((b)[1]))

// fp16 inputs, fp16 accum (cross terms; magnitudes ~2^-11 of main)
#define MMAH(c, a, b)                                                            \
    asm volatile("mma.sync.aligned.m16n8k16.row.col.f16.f16.f16.f16 "            \
        "{%0,%1}, {%2,%3,%4,%5}, {%6,%7}, {%0,%1};"                              \
        : "+r"((c)[0]), "+r"((c)[1])                                             \
        : "r"((a)[0]), "r"((a)[1]), "r"((a)[2]), "r"((a)[3]),                    \
          "r"((b)[0]), "r"((b)[1]))

#define LDSM_X4(r, addr)                                                         \
    asm volatile("ldmatrix.sync.aligned.m8n8.x4.shared.b16 {%0,%1,%2,%3}, [%4];" \
        : "=r"((r)[0]), "=r"((r)[1]), "=r"((r)[2]), "=r"((r)[3]) : "r"(addr))

#define LDSM_X2(r, addr)                                                         \
    asm volatile("ldmatrix.sync.aligned.m8n8.x2.shared.b16 {%0,%1}, [%2];"       \
        : "=r"((r)[0]), "=r"((r)[1]) : "r"(addr))

static __device__ __forceinline__ uint32_t smem_u32(const void* p) {
    uint32_t a;
    asm("{ .reg .u64 t; cvta.to.shared.u64 t, %1; cvt.u32.u64 %0, t; }" : "=r"(a) : "l"(p));
    return a;
}
static __device__ __forceinline__ void cp16(uint32_t dst, const void* src) {
    asm volatile("cp.async.ca.shared.global [%0], [%1], 16;" :: "r"(dst), "l"(src));
}
#define CP_COMMIT() asm volatile("cp.async.commit_group;" ::: "memory")
#define CP_WAIT1()  asm volatile("cp.async.wait_group 1;" ::: "memory")
#define CP_WAIT0()  asm volatile("cp.async.wait_group 0;" ::: "memory")

static __device__ __forceinline__ uint32_t pack_hl(float a, float b, float* ra, float* rb) {
    __half ha = __float2half_rn(a), hb = __float2half_rn(b);
    *ra = a - __half2float(ha);
    *rb = b - __half2float(hb);
    return ((uint32_t)__half_as_ushort(hb) << 16) | __half_as_ushort(ha);
}
static __device__ __forceinline__ uint32_t pack_h(float a, float b) {
    return ((uint32_t)__half_as_ushort(__float2half_rn(b)) << 16)
         | __half_as_ushort(__float2half_rn(a));
}
static __device__ __forceinline__ float2 h2f2(uint32_t p) {
    __half2 h = *reinterpret_cast<__half2*>(&p);
    return make_float2(__low2float(h), __high2float(h));
}
__device__ __forceinline__ uint32_t f2key(float f) {
    uint32_t u = __float_as_uint(f);
    return (u & 0x80000000u) ? ~u : (u | 0x80000000u);
}

// ---------------- fp32 -> fp16 hi/lo convert (ptrs as kernel args) ------------
__global__ __launch_bounds__(256) void cvt_kernel(
    const float* x, const float* wq, const float* wk, const float* wv, const float* wo,
    int nx4, int nw4)
{
    int t = blockIdx.y;
    int i = blockIdx.x * 256 + threadIdx.x;
    const float* s;
    __half *dh, *dl;
    int n4;
    switch (t) {
        case 0:  s = x;  dh = g_Xh;  dl = g_Xl;  n4 = nx4; break;
        case 1:  s = wq; dh = g_Wqh; dl = g_Wql; n4 = nw4; break;
        case 2:  s = wk; dh = g_Wkh; dl = g_Wkl; n4 = nw4; break;
        case 3:  s = wv; dh = g_Wvh; dl = g_Wvl; n4 = nw4; break;
        default: s = wo; dh = g_Woh; dl = g_Wol; n4 = nw4; break;
    }
    if (i >= n4) return;
    float4 v = ((const float4*)s)[i];
    float lx, ly, lz, lw;
    uint32_t h0 = pack_hl(v.x, v.y, &lx, &ly);
    uint32_t h1 = pack_hl(v.z, v.w, &lz, &lw);
    ((uint32_t*)dh)[i * 2]     = h0;
    ((uint32_t*)dh)[i * 2 + 1] = h1;
    ((uint32_t*)dl)[i * 2]     = pack_h(lx, ly);
    ((uint32_t*)dl)[i * 2 + 1] = pack_h(lz, lw);
}

// ---------------- projection GEMM: fp16x3 warp-mma + ldmatrix -----------------
#define PROJ_DYN 147456

__global__ __launch_bounds__(512) void proj_mma_kernel(
    int oproj,
    const float* __restrict__ bq, const float* __restrict__ bk,
    const float* __restrict__ bv, const float* __restrict__ bo,
    float* __restrict__ y)
{
    extern __shared__ __align__(16) uint32_t sm32[];

    const int tid   = threadIdx.x;
    const int lane  = tid & 31, w = tid >> 5;
    const int group = lane >> 2, qd = lane & 3;
    const int wm    = w & 7, wn = w >> 3;
    const int n0    = blockIdx.x * 128;
    const int m0    = blockIdx.y * 128;
    const int z     = oproj ? 3 : blockIdx.z;

    const uint32_t *Ah32, *Al32, *Bh32, *Bl32;
    const float* bias;
    if (oproj) { Ah32 = (const uint32_t*)g_Oh; Al32 = (const uint32_t*)g_Ol;
                 Bh32 = (const uint32_t*)g_Woh; Bl32 = (const uint32_t*)g_Wol; bias = bo; }
    else {
        Ah32 = (const uint32_t*)g_Xh; Al32 = (const uint32_t*)g_Xl;
        if (z == 0)      { Bh32 = (const uint32_t*)g_Wqh; Bl32 = (const uint32_t*)g_Wql; bias = bq; }
        else if (z == 1) { Bh32 = (const uint32_t*)g_Wkh; Bl32 = (const uint32_t*)g_Wkl; bias = bk; }
        else             { Bh32 = (const uint32_t*)g_Wvh; Bl32 = (const uint32_t*)g_Wvl; bias = bv; }
    }

    const uint32_t smb = smem_u32(sm32);
    const int r0 = wm * 16 + group;

    const uint32_t aOff = (((wm * 16 + (lane & 15)) * 36 + ((lane >> 4) << 2)) << 2);
    const uint32_t bOff = (((wn * 64 + (lane & 7)) * 36 + (((lane >> 3) & 1) << 2)) << 2);

    auto loadChunk = [&](int blk, int buf) {
        const int koff = blk * 32;
#pragma unroll
        for (int it = 0; it < 8; ++it) {
            int idx = tid + it * 512;
            int sel = idx >> 11;
            int arr = (idx >> 10) & 1;
            int rem = idx & 1023;
            int r = rem >> 3, ch = rem & 7;
            uint32_t dst = smb + (buf * 18432 + sel * 9216 + arr * 4608 + r * 36 + ch * 4) * 4;
            const uint32_t* src;
            if (sel == 0) src = (arr ? Al32 : Ah32) + (size_t)(m0 + r) * 384 + koff + ch * 4;
            else          src = (arr ? Bl32 : Bh32) + (size_t)(n0 + r) * 384 + koff + ch * 4;
            cp16(dst, src);
        }
    };

    float c8[8][4];
    uint32_t chf[8][2];
#pragma unroll
    for (int nt = 0; nt < 8; ++nt) {
#pragma unroll
        for (int i = 0; i < 4; ++i) c8[nt][i] = 0.f;
        chf[nt][0] = 0u; chf[nt][1] = 0u;
    }

    loadChunk(0, 0); CP_COMMIT();

    for (int blk = 0; blk < 12; ++blk) {
        __syncthreads();
        if (blk + 1 < 12) { loadChunk(blk + 1, (blk + 1) & 1); CP_COMMIT(); CP_WAIT1(); }
        else              { CP_WAIT0(); }
        __syncthreads();

        const uint32_t bufb = smb + ((blk & 1) * 18432 << 2);
        const uint32_t aH = bufb + aOff;
        const uint32_t aL = aH + (4608 << 2);
        const uint32_t bH = bufb + (9216 << 2) + bOff;
        const uint32_t bL = bH + (4608 << 2);

#pragma unroll
        for (int ks = 0; ks < 4; ++ks) {
            uint32_t ah[4], al[4];
            LDSM_X4(ah, aH + ks * 32);
            LDSM_X4(al, aL + ks * 32);
#pragma unroll
            for (int nt = 0; nt < 8; ++nt) {
                uint32_t bhv[2], blv[2];
                LDSM_X2(bhv, bH + nt * 1152 + ks * 32);
                LDSM_X2(blv, bL + nt * 1152 + ks * 32);
                MMA16816(c8[nt], ah, bhv);
                MMAH(chf[nt], ah, blv);
                MMAH(chf[nt], al, bhv);
            }
        }
    }

#pragma unroll
    for (int nt = 0; nt < 8; ++nt) {
        float2 x0 = h2f2(chf[nt][0]);
        float2 x1 = h2f2(chf[nt][1]);
        int n = n0 + wn * 64 + nt * 8 + qd * 2;
        float b0 = bias[n], b1 = bias[n + 1];
        int ma = m0 + r0, mb = ma + 8;
        float v00 = c8[nt][0] + x0.x + b0, v01 = c8[nt][1] + x0.y + b1;
        float v10 = c8[nt][2] + x1.x + b0, v11 = c8[nt][3] + x1.y + b1;
        if (oproj) {
            *(float2*)(y + (size_t)ma * DMODEL + n) = make_float2(v00, v01);
            *(float2*)(y + (size_t)mb * DMODEL + n) = make_float2(v10, v11);
        } else {
            int h = n >> 6, e = n & 63;
            if (z < 2) {
                __half* dh = (z == 0) ? g_Qh : g_Kh;
                __half* dl = (z == 0) ? g_Ql : g_Kl;
                int ba = ma >> 11, sa = ma & (SEQ - 1);
                int bb = mb >> 11, sb = mb & (SEQ - 1);
                size_t oa = ((((size_t)(ba * NHEADS + h)) * SEQ + sa) * HEADDIM + e) >> 1;
                size_t ob = ((((size_t)(bb * NHEADS + h)) * SEQ + sb) * HEADDIM + e) >> 1;
                float la, lb2, lc, ld;
                ((uint32_t*)dh)[oa] = pack_hl(v00, v01, &la, &lb2);
                ((uint32_t*)dl)[oa] = pack_h(la, lb2);
                ((uint32_t*)dh)[ob] = pack_hl(v10, v11, &lc, &ld);
                ((uint32_t*)dl)[ob] = pack_h(lc, ld);
            } else {
                int ba = ma >> 11, sa = ma & (SEQ - 1);
                int bb = mb >> 11, sb = mb & (SEQ - 1);
                size_t base0 = (((size_t)(ba * NHEADS + h)) * HEADDIM + e) * SEQ;
                size_t base1 = (((size_t)(bb * NHEADS + h)) * HEADDIM + e) * SEQ;
                __half h00 = __float2half_rn(v00); float l0 = v00 - __half2float(h00);
                __half h01 = __float2half_rn(v01); float l1 = v01 - __half2float(h01);
                __half h10 = __float2half_rn(v10); float l2 = v10 - __half2float(h10);
                __half h11 = __float2half_rn(v11); float l3 = v11 - __half2float(h11);
                g_Vth[base0 + sa]       = h00; g_Vtl[base0 + sa]       = __float2half_rn(l0);
                g_Vth[base0 + SEQ + sa] = h01; g_Vtl[base0 + SEQ + sa] = __float2half_rn(l1);
                g_Vth[base1 + sb]       = h10; g_Vtl[base1 + sb]       = __float2half_rn(l2);
                g_Vth[base1 + SEQ + sb] = h11; g_Vtl[base1 + SEQ + sb] = __float2half_rn(l3);
            }
        }
    }
}

// ------------- 3-pass (24-bit) radix select, pass-0 specialized ---------------
static __device__ __forceinline__ int resolve_digit(uint32_t* hist, int lane, int* want) {
    int c[8]; int lsum = 0;
#pragma unroll
    for (int i = 0; i < 8; ++i) { c[i] = (int)hist[lane * 8 + i]; lsum += c[i]; }
    int incl = lsum;
#pragma unroll
    for (int off = 1; off < 32; off <<= 1) {
        int t = __shfl_up_sync(0xffffffffu, incl, off);
        if (lane >= off) incl += t;
    }
    int total = __shfl_sync(0xffffffffu, incl, 31);
    int run = total - incl;
    int fd = -1, fw = 0;
#pragma unroll
    for (int i = 7; i >= 0; --i) {
        if (run < *want && run + c[i] >= *want) { fd = lane * 8 + i; fw = *want - run; }
        run += c[i];
    }
    unsigned bal = __ballot_sync(0xffffffffu, fd >= 0);
    int src = __ffs(bal) - 1;
    fd    = __shfl_sync(0xffffffffu, fd, src);
    *want = __shfl_sync(0xffffffffu, fw, src);
    return fd;
}

__device__ uint32_t warp_kth_key24(const float* __restrict__ row, int k,
                                   uint32_t* __restrict__ hist, int lane)
{
    uint32_t prefix = 0;
    int want = k;

    // pass 0: all lanes active — no act-ballot
    for (int i = lane; i < 256; i += 32) hist[i] = 0;
    __syncwarp();
    for (int i = lane; i < SEQ; i += 32) {
        int bin = f2key(row[i]) >> 24;
        unsigned p = __match_any_sync(0xffffffffu, bin);
        if ((int)__ffs(p) - 1 == lane) atomicAdd(&hist[bin], (uint32_t)__popc(p));
    }
    __syncwarp();
    prefix = (uint32_t)resolve_digit(hist, lane, &want) << 24;
    uint32_t mask_hi = 0xFF000000u;
    __syncwarp();

#pragma unroll
    for (int pass = 1; pass < 3; ++pass) {
        const int shift = 24 - pass * 8;
        for (int i = lane; i < 256; i += 32) hist[i] = 0;
        __syncwarp();
        for (int i = lane; i < SEQ; i += 32) {
            uint32_t key = f2key(row[i]);
            bool act = (((key ^ prefix) & mask_hi) == 0u);
            unsigned bal = __ballot_sync(0xffffffffu, act);
            if (act) {
                int bin = (key >> shift) & 0xFF;
                unsigned peers = __match_any_sync(bal, bin);
                if ((int)__ffs(peers) - 1 == lane)
                    atomicAdd(&hist[bin], (uint32_t)__popc(peers));
            }
        }
        __syncwarp();
        prefix |= (uint32_t)resolve_digit(hist, lane, &want) << shift;
        mask_hi |= 0xFFu << shift;
        __syncwarp();
    }
    return prefix;        // low byte zero: 24-bit threshold
}

// ---------------- attention (R13 structure, 3-pass select) --------------------
#define DYN_BYTES 147456

__global__ __launch_bounds__(ATHREADS) void attn_kernel()
{
    extern __shared__ __align__(16) uint32_t sm32[];

    __shared__ float s_inv[TQ];

    const int tid   = threadIdx.x;
    const int lane  = tid & 31, w = tid >> 5;
    const int group = lane >> 2, qd = lane & 3;
    const int wm    = w & 7;
    const int wn    = w >> 3;
    const int qt    = blockIdx.x & (NQT - 1);
    const int bh    = blockIdx.x >> 4;
    const int qrow0 = qt * TQ;

    const size_t hb = (size_t)bh * SEQ * HEADDIM;
    const uint32_t* qh32 = (const uint32_t*)(g_Qh + hb) + (size_t)qrow0 * 32;
    const uint32_t* ql32 = (const uint32_t*)(g_Ql + hb) + (size_t)qrow0 * 32;
    const uint32_t* kh32 = (const uint32_t*)(g_Kh + hb);
    const uint32_t* kl32 = (const uint32_t*)(g_Kl + hb);
    const uint32_t* vh32 = (const uint32_t*)(g_Vth + hb);
    const uint32_t* vl32 = (const uint32_t*)(g_Vtl + hb);
    float* Sp = g_S + (size_t)blockIdx.x * TQ * SEQ;
    uint32_t* Pp = (uint32_t*)g_P + (size_t)blockIdx.x * TQ * (SEQ / 2);

    const uint32_t smb = smem_u32(sm32);
    const int r0 = wm * 16 + group;

    // ================= phase 1: S = Q@K^T * 0.125 -> g_S ====================
    {
        uint32_t* QH = sm32;
        uint32_t* QL = sm32 + 4608;

#pragma unroll
        for (int it = 0; it < 8; ++it) {
            int idx = tid + it * ATHREADS;
            int r = idx >> 5, c = idx & 31;
            QH[r * 36 + c] = qh32[(size_t)r * 32 + c];
            QL[r * 36 + c] = ql32[(size_t)r * 32 + c];
        }

        auto loadK = [&](int blk, int buf) {
            const int j0 = blk * 128;
            const uint32_t dstb = smb + (9216 + buf * 9216) * 4;
#pragma unroll
            for (int it = 0; it < 4; ++it) {
                int idx = tid + it * ATHREADS;
                int arr = idx >> 10, rem = idx & 1023;
                int r = rem >> 3, ch = rem & 7;
                uint32_t dst = dstb + (arr * 4608 + r * 36 + ch * 4) * 4;
                const uint32_t* src = (arr ? kl32 : kh32) + (size_t)(j0 + r) * 32 + ch * 4;
                cp16(dst, src);
            }
        };

        const uint32_t aH = smb + (((wm * 16 + (lane & 15)) * 36 + ((lane >> 4) << 2)) << 2);
        const uint32_t aL = aH + (4608 << 2);
        const uint32_t bOff = (((wn * 64 + (lane & 7)) * 36 + (((lane >> 3) & 1) << 2)) << 2);

        loadK(0, 0); CP_COMMIT();
        __syncthreads();

        uint32_t qfh[4][4], qfl[4][4];
#pragma unroll
        for (int ks = 0; ks < 4; ++ks) {
            LDSM_X4(qfh[ks], aH + ks * 32);
            LDSM_X4(qfl[ks], aL + ks * 32);
        }

        for (int blk = 0; blk < 16; ++blk) {
            __syncthreads();
            if (blk + 1 < 16) { loadK(blk + 1, (blk + 1) & 1); CP_COMMIT(); CP_WAIT1(); }
            else              { CP_WAIT0(); }
            __syncthreads();

            const uint32_t bH = smb + ((9216 + (blk & 1) * 9216) << 2) + bOff;
            const uint32_t bL = bH + (4608 << 2);
            const int j0 = blk * 128;

            float c8[8][4];
            uint32_t chf[8][2];
#pragma unroll
            for (int nt = 0; nt < 8; ++nt) {
#pragma unroll
                for (int i = 0; i < 4; ++i) c8[nt][i] = 0.f;
                chf[nt][0] = 0u; chf[nt][1] = 0u;
            }

#pragma unroll
            for (int ks = 0; ks < 4; ++ks) {
#pragma unroll
                for (int nt = 0; nt < 8; ++nt) {
                    uint32_t bhv[2], blv[2];
                    LDSM_X2(bhv, bH + nt * 1152 + ks * 32);
                    LDSM_X2(blv, bL + nt * 1152 + ks * 32);
                    MMA16816(c8[nt], qfh[ks], bhv);
                    MMAH(chf[nt], qfh[ks], blv);
                    MMAH(chf[nt], qfl[ks], bhv);
                }
            }
#pragma unroll
            for (int nt = 0; nt < 8; ++nt) {
                float2 x0 = h2f2(chf[nt][0]);
                float2 x1 = h2f2(chf[nt][1]);
                int col = j0 + wn * 64 + nt * 8 + qd * 2;
                float2 v0 = { (c8[nt][0] + x0.x) * 0.125f, (c8[nt][1] + x0.y) * 0.125f };
                float2 v1 = { (c8[nt][2] + x1.x) * 0.125f, (c8[nt][3] + x1.y) * 0.125f };
                *(float2*)(Sp + (size_t)r0 * SEQ + col)       = v0;
                *(float2*)(Sp + (size_t)(r0 + 8) * SEQ + col) = v1;
            }
        }
    }
    __syncthreads();

    // ====== phase 2: 3-pass top-k; unnormalized fp16 P -> g_P ==============
    {
        float* rowbuf = (float*)sm32 + w * 2048;
        uint32_t* hist = sm32 + 32768 + w * 256;
        for (int t = 0; t < 8; ++t) {
            int r = w * 8 + t;
            const float* grow = Sp + (size_t)r * SEQ;
            float mx = -3.4e38f;
            for (int it = 0; it < 16; ++it) {
                float4 v = ((const float4*)grow)[lane + it * 32];
                ((float4*)rowbuf)[lane + it * 32] = v;
                mx = fmaxf(mx, fmaxf(fmaxf(v.x, v.y), fmaxf(v.z, v.w)));
            }
#pragma unroll
            for (int off = 16; off; off >>= 1)
                mx = fmaxf(mx, __shfl_xor_sync(0xffffffffu, mx, off));
            __syncwarp();
            uint32_t thr = warp_kth_key24(rowbuf, KKEEP, hist, lane);
            float sum = 0.f;
            uint32_t* gpr = Pp + (size_t)r * (SEQ / 2);
            for (int it = 0; it < 32; ++it) {
                float2 s2 = ((const float2*)rowbuf)[it * 32 + lane];
                float e0 = (f2key(s2.x) >= thr) ? __expf(s2.x - mx) : 0.f;
                float e1 = (f2key(s2.y) >= thr) ? __expf(s2.y - mx) : 0.f;
                sum += e0 + e1;
                gpr[it * 32 + lane] = pack_h(e0, e1);
            }
#pragma unroll
            for (int off = 16; off; off >>= 1)
                sum += __shfl_xor_sync(0xffffffffu, sum, off);
            if (lane == 0) s_inv[r] = 1.0f / sum;
            __syncwarp();
        }
    }
    __syncthreads();

    // ============ phase 3: O = (P @ (Vh+Vl)) * inv  (pure GEMM) =============
    {
        auto loadPV = [&](int blk, int buf) {
            const int j32 = blk * 64;
            const uint32_t pdst = smb + (buf * 8704) * 4;
#pragma unroll
            for (int it = 0; it < 4; ++it) {
                int idx = tid + it * ATHREADS;
                int r = idx >> 4, ch = idx & 15;
                cp16(pdst + (r * 68 + ch * 4) * 4,
                     Pp + (size_t)r * (SEQ / 2) + j32 + ch * 4);
            }
            const uint32_t vdst = smb + (17408 + buf * 8704) * 4;
#pragma unroll
            for (int it = 0; it < 4; ++it) {
                int idx = tid + it * ATHREADS;
                int arr = idx >> 10, rem = idx & 1023;
                int r = rem >> 4, ch = rem & 15;
                cp16(vdst + (arr * 4352 + r * 68 + ch * 4) * 4,
                     (arr ? vl32 : vh32) + (size_t)r * 1024 + j32 + ch * 4);
            }
        };

        float c8[4][4];
#pragma unroll
        for (int nt = 0; nt < 4; ++nt)
#pragma unroll
            for (int i = 0; i < 4; ++i) c8[nt][i] = 0.f;

        const uint32_t aOff3 = (((wm * 16 + (lane & 15)) * 68 + ((lane >> 4) << 2)) << 2);
        const uint32_t bOff3 = (((wn * 32 + (lane & 7)) * 68 + (((lane >> 3) & 1) << 2)) << 2);

        loadPV(0, 0); CP_COMMIT();

        for (int blk = 0; blk < 16; ++blk) {
            __syncthreads();
            if (blk + 1 < 16) { loadPV(blk + 1, (blk + 1) & 1); CP_COMMIT(); CP_WAIT1(); }
            else              { CP_WAIT0(); }
            __syncthreads();

            const uint32_t aP  = smb + (((blk & 1) * 8704) << 2) + aOff3;
            const uint32_t bH3 = smb + ((17408 + (blk & 1) * 8704) << 2) + bOff3;
            const uint32_t bL3 = bH3 + (4352 << 2);

#pragma unroll
            for (int ks = 0; ks < 8; ++ks) {
                uint32_t ah[4];
                LDSM_X4(ah, aP + ks * 32);
#pragma unroll
                for (int nt = 0; nt < 4; ++nt) {
                    uint32_t bhv[2], blv[2];
                    LDSM_X2(bhv, bH3 + nt * 2176 + ks * 32);
                    LDSM_X2(blv, bL3 + nt * 2176 + ks * 32);
                    MMA16816(c8[nt], ah, bhv);
                    MMA16816(c8[nt], ah, blv);
                }
            }
        }

        const int b_ = bh / NHEADS, h = bh % NHEADS;
        const float inv0 = s_inv[r0], inv1 = s_inv[r0 + 8];
#pragma unroll
        for (int nt = 0; nt < 4; ++nt) {
            int e = h * HEADDIM + wn * 32 + nt * 8 + qd * 2;
            int s0 = qrow0 + r0, s1 = s0 + 8;
            size_t o0 = (((size_t)(b_ * SEQ + s0)) * DMODEL + e) >> 1;
            size_t o1 = (((size_t)(b_ * SEQ + s1)) * DMODEL + e) >> 1;
            float l0, l1, l2, l3;
            ((uint32_t*)g_Oh)[o0] = pack_hl(c8[nt][0] * inv0, c8[nt][1] * inv0, &l0, &l1);
            ((uint32_t*)g_Ol)[o0] = pack_h(l0, l1);
            ((uint32_t*)g_Oh)[o1] = pack_hl(c8[nt][2] * inv1, c8[nt][3] * inv1, &l2, &l3);
            ((uint32_t*)g_Ol)[o1] = pack_h(l2, l3);
        }
    }
}

// ---------------- launch ------------------------------------------------------
extern "C" void kernel_launch(void* const* d_in, const int* in_sizes, int n_in,
                              void* d_out, int out_size)
{
    const float* x  = (const float*)d_in[0];
    const float* Wq = (const float*)d_in[1];
    const float* bq = (const float*)d_in[2];
    const float* Wk = (const float*)d_in[3];
    const float* bk = (const float*)d_in[4];
    const float* Wv = (const float*)d_in[5];
    const float* bv = (const float*)d_in[6];
    const float* Wo = (const float*)d_in[7];
    const float* bo = (const float*)d_in[8];
    float* y = (float*)d_out;

    const int nx4 = MROWS * DMODEL / 4;
    const int nw4 = DMODEL * DMODEL / 4;

    dim3 gc((nx4 + 255) / 256, 5);
    cvt_kernel<<<gc, 256>>>(x, Wq, Wk, Wv, Wo, nx4, nw4);

    cudaFuncSetAttribute(proj_mma_kernel, cudaFuncAttributeMaxDynamicSharedMemorySize, PROJ_DYN);
    dim3 gq(DMODEL / 128, MROWS / 128, 3);
    proj_mma_kernel<<<gq, 512, PROJ_DYN>>>(0, bq, bk, bv, bo, y);

    cudaFuncSetAttribute(attn_kernel, cudaFuncAttributeMaxDynamicSharedMemorySize, DYN_BYTES);
    attn_kernel<<<BATCH * NHEADS * NQT, ATHREADS, DYN_BYTES>>>();

    dim3 go(DMODEL / 128, MROWS / 128, 1);
    proj_mma_kernel<<<go, 512, PROJ_DYN>>>(1, bq, bk, bv, bo, y);
}